// round 14
// baseline (speedup 1.0000x reference)
#include <cuda_runtime.h>
#include <cuda_bf16.h>

#define BINS        10
#define THREADS     256
#define CTAS_PER_SM 5
#define GRID        (148 * CTAS_PER_SM)   // 740
#define NWARPS      (THREADS / 32)        // 8

// Global scratch (allocation-free). Invariant: zero at every kernel entry —
// zero-initialized at load, last CTA of each run resets after writing out.
__device__ float        g_binS[BINS];
__device__ float        g_binC[BINS];
__device__ unsigned int g_ticket;

// 256-bit global load (sm_100+): one LDG.E.256 per 8 floats.
__device__ __forceinline__ void ldg256(const float* __restrict__ p, float v[8]) {
    asm("ld.global.nc.v8.f32 {%0,%1,%2,%3,%4,%5,%6,%7}, [%8];"
        : "=f"(v[0]), "=f"(v[1]), "=f"(v[2]), "=f"(v[3]),
          "=f"(v[4]), "=f"(v[5]), "=f"(v[6]), "=f"(v[7])
        : "l"(p));
}

// Bin index matches reference bit-for-bit: g = |p-t| fp32, idx = trunc(g*10)
// clipped to 9. bce = -log(t ? p : 1-p) = -log(1-g) for t in {0,1}.
// Slot hist[idx*THREADS + tid] is PRIVATE to thread tid (single writer) ->
// conflict-free, deterministic, and needs no barrier until the epilogue.
__device__ __forceinline__ void ghm_accum(float p, float t, float2* hist_tid) {
    float g   = fabsf(p - t);
    int   idx = min((int)(g * 10.0f), BINS - 1);
    float bce = -__logf(1.0f - g);
    float2* slot = hist_tid + idx * THREADS;
    float2  a = *slot;
    a.x += bce;
    a.y += 1.0f;
    *slot = a;
}

__device__ __forceinline__ void ghm_accum8(const float p[8], const float t[8],
                                           float2* h) {
    #pragma unroll
    for (int k = 0; k < 8; k++) ghm_accum(p[k], t[k], h);
}

__global__ void __launch_bounds__(THREADS, CTAS_PER_SM)
ghm_fused_kernel(const float* __restrict__ inp,
                 const float* __restrict__ tgt,
                 int n8, int n,
                 float* __restrict__ out) {
    __shared__ float2 hist[BINS * THREADS];   // 20 KB: [bin][tid], thread-private
    __shared__ bool   s_is_last;
    const int tid  = threadIdx.x;
    const int lane = tid & 31;
    const int wid  = tid >> 5;

    const int stride = GRID * THREADS;
    int i = blockIdx.x * THREADS + tid;

    // Issue the first batch's loads FIRST (600-cyc latency overlaps the
    // histogram zeroing below — no barrier needed: slots are thread-private).
    float p[8], t[8];
    bool have = (i < n8);
    if (have) {
        ldg256(inp + (size_t)i * 8, p);
        ldg256(tgt + (size_t)i * 8, t);
    }

    #pragma unroll
    for (int b = 0; b < BINS; b++)
        hist[b * THREADS + tid] = make_float2(0.0f, 0.0f);

    float2* hist_tid = &hist[tid];

    // Software-pipelined loop over float8 blocks: next block's two LDG.256
    // are issued before the current block's 8 smem-RMWs drain.
    if (have) {
        float q[8], u[8];
        int j = i + stride;
        for (; j < n8; j += stride) {
            ldg256(inp + (size_t)j * 8, q);
            ldg256(tgt + (size_t)j * 8, u);
            ghm_accum8(p, t, hist_tid);
            #pragma unroll
            for (int k = 0; k < 8; k++) { p[k] = q[k]; t[k] = u[k]; }
        }
        ghm_accum8(p, t, hist_tid);
    }
    // Scalar tail (n not divisible by 8; empty for this shape).
    for (int j = n8 * 8 + blockIdx.x * THREADS + tid; j < n; j += stride)
        ghm_accum(inp[j], tgt[j], hist_tid);

    __syncthreads();   // all private RMWs done before cross-thread reduction

    // Bin-per-warp epilogue: warp w reduces bin w; warps 0,1 also take
    // bins 8,9. Each lane folds 8 slots (consecutive-lane addressing,
    // conflict-free), then 5 shuffle rounds, lane 0 pushes the CTA total.
    #pragma unroll
    for (int pass = 0; pass < 2; pass++) {
        int b = (pass == 0) ? wid : (wid < 2 ? wid + 8 : -1);
        if (b >= 0 && b < BINS) {
            float2 v = make_float2(0.0f, 0.0f);
            #pragma unroll
            for (int c = 0; c < THREADS / 32; c++) {
                float2 h = hist[b * THREADS + c * 32 + lane];
                v.x += h.x;
                v.y += h.y;
            }
            #pragma unroll
            for (int off = 16; off > 0; off >>= 1) {
                v.x += __shfl_down_sync(0xFFFFFFFFu, v.x, off);
                v.y += __shfl_down_sync(0xFFFFFFFFu, v.y, off);
            }
            if (lane == 0) {
                atomicAdd(&g_binS[b], v.x);
                atomicAdd(&g_binC[b], v.y);
            }
        }
    }
    __threadfence();
    __syncthreads();

    // Last CTA finalizes and resets state for the next graph replay.
    if (tid == 0)
        s_is_last = (atomicAdd(&g_ticket, 1u) == GRID - 1);
    __syncthreads();

    if (s_is_last && tid == 0) {
        __threadfence();
        float nb = 0.0f, accv = 0.0f;
        #pragma unroll
        for (int b = 0; b < BINS; b++) {
            float c = __ldcg(&g_binC[b]);
            float s = __ldcg(&g_binS[b]);
            if (c > 0.0f) {
                nb   += 1.0f;
                accv += s / c;
            }
        }
        out[0] = accv / fmaxf(nb, 1.0f);
        #pragma unroll
        for (int b = 0; b < BINS; b++) { g_binS[b] = 0.0f; g_binC[b] = 0.0f; }
        g_ticket = 0u;
    }
}

extern "C" void kernel_launch(void* const* d_in, const int* in_sizes, int n_in,
                              void* d_out, int out_size) {
    const float* inp = (const float*)d_in[0];
    const float* tgt = (const float*)d_in[1];
    float* out = (float*)d_out;
    int n  = in_sizes[0];
    int n8 = n >> 3;

    ghm_fused_kernel<<<GRID, THREADS>>>(inp, tgt, n8, n, out);
}

// round 15
// speedup vs baseline: 1.0770x; 1.0770x over previous
#include <cuda_runtime.h>
#include <cuda_bf16.h>

#define BINS        10
#define THREADS     256
#define CTAS_PER_SM 5
#define GRID        (148 * CTAS_PER_SM)   // 740
#define NWARPS      (THREADS / 32)

// Global scratch (allocation-free). Invariant: zero at every kernel entry —
// zero-initialized at load, last CTA of each run resets after writing out.
__device__ float        g_binS[BINS];
__device__ float        g_binC[BINS];
__device__ unsigned int g_ticket;

// 256-bit global load (sm_100+): one LDG.E.256 per 8 floats.
__device__ __forceinline__ void ldg256(const float* __restrict__ p, float v[8]) {
    asm("ld.global.nc.v8.f32 {%0,%1,%2,%3,%4,%5,%6,%7}, [%8];"
        : "=f"(v[0]), "=f"(v[1]), "=f"(v[2]), "=f"(v[3]),
          "=f"(v[4]), "=f"(v[5]), "=f"(v[6]), "=f"(v[7])
        : "l"(p));
}

// Bin index matches reference bit-for-bit: g = |p-t| in fp32,
// idx = trunc(g*10) clipped to 9 (g >= 0 so trunc == floor).
// bce = -(t*log(p) + (1-t)*log(1-p)) = -log(1 - |p-t|) for t in {0,1}.
// Per-thread-private slot hist[idx*THREADS + tid]: 32 lanes of a warp hit 32
// consecutive 8B slots -> conflict-free regardless of idx.
__device__ __forceinline__ void ghm_accum(float p, float t, float2* hist_tid) {
    float g   = fabsf(p - t);
    int   idx = min((int)(g * 10.0f), BINS - 1);
    float bce = -__logf(1.0f - g);
    float2* slot = hist_tid + idx * THREADS;
    float2  a = *slot;
    a.x += bce;
    a.y += 1.0f;
    *slot = a;
}

__device__ __forceinline__ void ghm_accum8(const float p[8], const float t[8],
                                           float2* h) {
    #pragma unroll
    for (int k = 0; k < 8; k++) ghm_accum(p[k], t[k], h);
}

__global__ void __launch_bounds__(THREADS, CTAS_PER_SM)
ghm_fused_kernel(const float* __restrict__ inp,
                 const float* __restrict__ tgt,
                 int n8, int n,
                 float* __restrict__ out) {
    __shared__ float2 hist[BINS * THREADS];     // 20 KB: [bin][tid]
    __shared__ float2 scratch[BINS][NWARPS];    // warp partials
    __shared__ bool   s_is_last;
    const int tid  = threadIdx.x;
    const int lane = tid & 31;
    const int wid  = tid >> 5;

    #pragma unroll
    for (int b = 0; b < BINS; b++)
        hist[b * THREADS + tid] = make_float2(0.0f, 0.0f);
    __syncthreads();

    float2* hist_tid = &hist[tid];
    const int stride = GRID * THREADS;

    // Software-pipelined loop over float8 blocks: the next block's two
    // LDG.256 are issued before the current block's 8 smem-RMWs.
    int i = blockIdx.x * THREADS + tid;
    if (i < n8) {
        float p[8], t[8], q[8], u[8];
        ldg256(inp + (size_t)i * 8, p);
        ldg256(tgt + (size_t)i * 8, t);
        int j = i + stride;
        for (; j < n8; j += stride) {
            ldg256(inp + (size_t)j * 8, q);
            ldg256(tgt + (size_t)j * 8, u);
            ghm_accum8(p, t, hist_tid);
            #pragma unroll
            for (int k = 0; k < 8; k++) { p[k] = q[k]; t[k] = u[k]; }
        }
        ghm_accum8(p, t, hist_tid);
    }
    // Scalar tail (n not divisible by 8).
    for (int j = n8 * 8 + blockIdx.x * THREADS + tid; j < n; j += stride)
        ghm_accum(inp[j], tgt[j], hist_tid);

    __syncthreads();

    // Warp-shuffle reduction: each warp reduces its 32 private slots per bin.
    #pragma unroll
    for (int b = 0; b < BINS; b++) {
        float2 v = hist[b * THREADS + tid];
        #pragma unroll
        for (int off = 16; off > 0; off >>= 1) {
            v.x += __shfl_down_sync(0xFFFFFFFFu, v.x, off);
            v.y += __shfl_down_sync(0xFFFFFFFFu, v.y, off);
        }
        if (lane == 0) scratch[b][wid] = v;
    }
    __syncthreads();

    // Fold warp partials and push per-CTA totals into global bins.
    if (tid < BINS) {
        float2 s = scratch[tid][0];
        #pragma unroll
        for (int w = 1; w < NWARPS; w++) {
            s.x += scratch[tid][w].x;
            s.y += scratch[tid][w].y;
        }
        atomicAdd(&g_binS[tid], s.x);
        atomicAdd(&g_binC[tid], s.y);
    }
    __threadfence();
    __syncthreads();

    // Last CTA finalizes and resets state for the next graph replay.
    if (tid == 0)
        s_is_last = (atomicAdd(&g_ticket, 1u) == GRID - 1);
    __syncthreads();

    if (s_is_last && tid == 0) {
        __threadfence();
        float nb = 0.0f, accv = 0.0f;
        #pragma unroll
        for (int b = 0; b < BINS; b++) {
            float c = __ldcg(&g_binC[b]);
            float s = __ldcg(&g_binS[b]);
            if (c > 0.0f) {
                nb   += 1.0f;
                accv += s / c;
            }
        }
        out[0] = accv / fmaxf(nb, 1.0f);
        #pragma unroll
        for (int b = 0; b < BINS; b++) { g_binS[b] = 0.0f; g_binC[b] = 0.0f; }
        g_ticket = 0u;
    }
}

extern "C" void kernel_launch(void* const* d_in, const int* in_sizes, int n_in,
                              void* d_out, int out_size) {
    const float* inp = (const float*)d_in[0];
    const float* tgt = (const float*)d_in[1];
    float* out = (float*)d_out;
    int n  = in_sizes[0];
    int n8 = n >> 3;

    ghm_fused_kernel<<<GRID, THREADS>>>(inp, tgt, n8, n, out);
}

// round 16
// speedup vs baseline: 1.0818x; 1.0045x over previous
#include <cuda_runtime.h>
#include <cuda_bf16.h>

#define BINS        10
#define THREADS     256
#define CTAS_PER_SM 5                 // 48-reg budget: room for the pipeline
#define GRID        (148 * CTAS_PER_SM)   // 740

// Global scratch (allocation-free). Invariant: zero at every kernel entry —
// zero-initialized at load, last CTA of each run resets after writing out.
__device__ float        g_binS[BINS];
__device__ float        g_binC[BINS];
__device__ unsigned int g_ticket;

// Bin index matches reference bit-for-bit: g = |p-t| in fp32,
// idx = trunc(g*10) clipped to 9 (g >= 0 so trunc == floor).
// bce = -(t*log(p) + (1-t)*log(1-p)) = -log(1 - |p-t|) for t in {0,1}.
// Per-thread-private slot hist[idx*THREADS + tid]: 32 lanes of a warp hit 32
// consecutive 8B slots -> conflict-free regardless of idx.
__device__ __forceinline__ void ghm_accum(float p, float t, float2* hist_tid) {
    float g   = fabsf(p - t);
    int   idx = min((int)(g * 10.0f), BINS - 1);
    float bce = -__logf(1.0f - g);
    float2* slot = hist_tid + idx * THREADS;
    float2  a = *slot;
    a.x += bce;
    a.y += 1.0f;
    *slot = a;
}

__device__ __forceinline__ void ghm_accum4(float4 p, float4 t, float2* h) {
    ghm_accum(p.x, t.x, h);
    ghm_accum(p.y, t.y, h);
    ghm_accum(p.z, t.z, h);
    ghm_accum(p.w, t.w, h);
}

__global__ void __launch_bounds__(THREADS, CTAS_PER_SM)
ghm_fused_kernel(const float* __restrict__ inp,
                 const float* __restrict__ tgt,
                 int n4, int n,
                 float* __restrict__ out) {
    __shared__ float2 hist[BINS * THREADS];   // 20 KB: [bin][tid]
    __shared__ bool   s_is_last;
    const int tid = threadIdx.x;

    #pragma unroll
    for (int b = 0; b < BINS; b++)
        hist[b * THREADS + tid] = make_float2(0.0f, 0.0f);
    __syncthreads();

    float2* hist_tid = &hist[tid];

    const float4* __restrict__ P4 = (const float4*)inp;
    const float4* __restrict__ T4 = (const float4*)tgt;
    const int stride = GRID * THREADS;

    int i = blockIdx.x * THREADS + tid;

    // Software-pipelined loop: batch k+1's 4 LDG.128 are issued BEFORE
    // batch k's 8 smem-RMWs, so every warp keeps ~2 KB of reads in flight
    // through the chain phase.
    if (i + stride < n4) {
        float4 p0 = P4[i];
        float4 t0 = T4[i];
        float4 p1 = P4[i + stride];
        float4 t1 = T4[i + stride];
        i += 2 * stride;
        for (; i + stride < n4; i += 2 * stride) {
            float4 q0 = P4[i];
            float4 u0 = T4[i];
            float4 q1 = P4[i + stride];
            float4 u1 = T4[i + stride];
            ghm_accum4(p0, t0, hist_tid);
            ghm_accum4(p1, t1, hist_tid);
            p0 = q0; t0 = u0; p1 = q1; t1 = u1;
        }
        ghm_accum4(p0, t0, hist_tid);
        ghm_accum4(p1, t1, hist_tid);
    }
    // Remainder float4 pairs (0..2 per thread).
    for (; i < n4; i += stride) {
        float4 p = P4[i];
        float4 t = T4[i];
        ghm_accum4(p, t, hist_tid);
    }
    // Scalar tail (n not divisible by 4).
    for (int j = n4 * 4 + blockIdx.x * THREADS + tid; j < n; j += stride)
        ghm_accum(inp[j], tgt[j], hist_tid);

    __syncthreads();

    // CTA tree reduction over the thread dimension, all bins per level.
    for (int s = THREADS / 2; s > 0; s >>= 1) {
        if (tid < s) {
            #pragma unroll
            for (int b = 0; b < BINS; b++) {
                float2 a = hist[b * THREADS + tid];
                float2 c = hist[b * THREADS + tid + s];
                hist[b * THREADS + tid] = make_float2(a.x + c.x, a.y + c.y);
            }
        }
        __syncthreads();
    }

    // Per-CTA partials into global bins.
    if (tid < BINS) {
        atomicAdd(&g_binS[tid], hist[tid * THREADS].x);
        atomicAdd(&g_binC[tid], hist[tid * THREADS].y);
    }
    __threadfence();
    __syncthreads();

    // Last CTA finalizes and resets state for the next graph replay.
    if (tid == 0)
        s_is_last = (atomicAdd(&g_ticket, 1u) == GRID - 1);
    __syncthreads();

    if (s_is_last && tid == 0) {
        __threadfence();
        float nb = 0.0f, accv = 0.0f;
        #pragma unroll
        for (int b = 0; b < BINS; b++) {
            float c = __ldcg(&g_binC[b]);
            float s = __ldcg(&g_binS[b]);
            if (c > 0.0f) {
                nb   += 1.0f;
                accv += s / c;
            }
        }
        out[0] = accv / fmaxf(nb, 1.0f);
        #pragma unroll
        for (int b = 0; b < BINS; b++) { g_binS[b] = 0.0f; g_binC[b] = 0.0f; }
        g_ticket = 0u;
    }
}

extern "C" void kernel_launch(void* const* d_in, const int* in_sizes, int n_in,
                              void* d_out, int out_size) {
    const float* inp = (const float*)d_in[0];
    const float* tgt = (const float*)d_in[1];
    float* out = (float*)d_out;
    int n  = in_sizes[0];
    int n4 = n >> 2;

    ghm_fused_kernel<<<GRID, THREADS>>>(inp, tgt, n4, n, out);
}